// round 16
// baseline (speedup 1.0000x reference)
#include <cuda_runtime.h>
#include <cuda_bf16.h>
#include <mma.h>
#include <cstddef>
#include <cstdint>

using namespace nvcuda;

// ---------------------------------------------------------------------------
// VQ-VAE forward. NUMERICS:
//  - Encoder GEMMs 1-2 + VQ: BIT-FROZEN (argmin must never flip).
//  - Decoder: hybrid-warp GEMM: 8 warps wmma bf16x3 (rows 0-111) + 2 warps
//    FFMA2 fp32 (rows 112-127, reconstructed hi+lo) in the SAME CTA, so
//    tensor and fma pipes superpose. cp.async double-buffered.
// ---------------------------------------------------------------------------

#define B_      8192
#define IN_DIM  1024
#define HID     2048
#define KCODES  512
#define DDIM    64
#define LLAT    32

typedef unsigned long long ull;
typedef __nv_bfloat16 bf16;

__device__ float g_h [(size_t)B_ * HID];      // G1 output (fp32, frozen)
__device__ float g_Bk[KCODES];
__device__ bf16 g_zqhi[(size_t)B_ * HID];
__device__ bf16 g_zqlo[(size_t)B_ * HID];
__device__ bf16 g_h2hi[(size_t)B_ * HID];
__device__ bf16 g_h2lo[(size_t)B_ * HID];
__device__ bf16 g_w3hi[(size_t)HID * HID];
__device__ bf16 g_w3lo[(size_t)HID * HID];
__device__ bf16 g_w4hi[(size_t)HID * IN_DIM];
__device__ bf16 g_w4lo[(size_t)HID * IN_DIM];
__device__ bf16 g_ehi[KCODES * DDIM];
__device__ bf16 g_elo[KCODES * DDIM];

// ---- packed f32x2 helpers ---------------------------------------------------
__device__ __forceinline__ ull pack_dup(unsigned u) {
    ull r;
    asm("mov.b64 %0, {%1, %1};" : "=l"(r) : "r"(u));
    return r;
}
__device__ __forceinline__ void ffma2(ull& acc, ull a, ull b) {
    asm("fma.rn.f32x2 %0, %1, %2, %0;" : "+l"(acc) : "l"(a), "l"(b));
}

// ---- cp.async helpers -------------------------------------------------------
__device__ __forceinline__ uint32_t smem_u32(const void* p) {
    uint32_t a;
    asm("{ .reg .u64 t; cvta.to.shared.u64 t, %1; cvt.u32.u64 %0, t; }"
        : "=r"(a) : "l"(p));
    return a;
}
__device__ __forceinline__ void cp16(uint32_t dst, const void* src) {
    asm volatile("cp.async.cg.shared.global [%0], [%1], 16;"
                 :: "r"(dst), "l"(src) : "memory");
}
#define CP_COMMIT() asm volatile("cp.async.commit_group;" ::: "memory")
#define CP_WAIT1()  asm volatile("cp.async.wait_group 1;" ::: "memory")
#define CP_WAIT0()  asm volatile("cp.async.wait_group 0;" ::: "memory")

// bf16 (as ushort) -> fp32 exact
__device__ __forceinline__ float bf2f(unsigned short s) {
    return __uint_as_float(((uint32_t)s) << 16);
}

// ---------------------------------------------------------------------------
__global__ void bk_kernel(const float* __restrict__ emb, float* __restrict__ Bk)
{
    int gwarp = (blockIdx.x * blockDim.x + threadIdx.x) >> 5;
    int lane  = threadIdx.x & 31;
    if (gwarp < KCODES) {
        const float* e = emb + (size_t)gwarp * DDIM;
        float e0 = e[2 * lane], e1 = e[2 * lane + 1];
        float p = __fadd_rn(__fmul_rn(e0, e0), __fmul_rn(e1, e1));
        #pragma unroll
        for (int off = 16; off > 0; off >>= 1)
            p = __fadd_rn(p, __shfl_down_sync(0xffffffffu, p, off));
        if (lane == 0) Bk[gwarp] = p;
    }
}

// ---------------------------------------------------------------------------
__global__ __launch_bounds__(256)
void splitf(const float* __restrict__ src, bf16* __restrict__ hi,
            bf16* __restrict__ lo)
{
    size_t i = ((size_t)blockIdx.x * 256 + threadIdx.x) * 4;
    float4 v = *(const float4*)(src + i);
    float vv[4] = {v.x, v.y, v.z, v.w};
    ull hp = 0, lp = 0;
    #pragma unroll
    for (int e = 0; e < 4; e++) {
        bf16 h = __float2bfloat16_rn(vv[e]);
        bf16 l = __float2bfloat16_rn(vv[e] - __bfloat162float(h));
        hp |= (ull)__bfloat16_as_ushort(h) << (16 * e);
        lp |= (ull)__bfloat16_as_ushort(l) << (16 * e);
    }
    *(ull*)(hi + i) = hp;
    *(ull*)(lo + i) = lp;
}

// ---------------------------------------------------------------------------
// Hybrid decoder GEMM. 320 threads: warps 0-7 wmma bf16x3 rows 0..111,
// warps 8-9 scalar FFMA2 rows 112..127 on reconstructed fp32.
// MODE 0: C fp32, no relu (G4).   MODE 1: relu, bf16 hi/lo out (G3).
// Dynamic smem layout:
//   buf0 @0, buf1 @37888   (As_hi[128x40]@+0, As_lo@+10240,
//                           Bs_hi[32x136]@+20480, Bs_lo@+29184)
//   bias_s (16x128 f32) @75776
//   Bsf (32x132 f32)    @83968
//   Asf (16x33 f32)     @100864
// ---------------------------------------------------------------------------
#define BUF_BYTES 37888
#define SM_BIAS   75776
#define SM_BSF    83968
#define SM_ASF    100864
#define SM_TOTAL  102976

template<int MODE>
__global__ __launch_bounds__(320)
void gemm_wmma(const bf16* __restrict__ Ahi, const bf16* __restrict__ Alo,
               const bf16* __restrict__ Bhi, const bf16* __restrict__ Blo,
               const float* __restrict__ bias, float* __restrict__ Cf,
               bf16* __restrict__ Chi, bf16* __restrict__ Clo,
               int N, int K)
{
    extern __shared__ __align__(16) char dsm[];
    float* bias_s = (float*)(dsm + SM_BIAS);
    float* Bsf    = (float*)(dsm + SM_BSF);
    float* Asf    = (float*)(dsm + SM_ASF);

    const int tid = threadIdx.x;
    const int wid = tid >> 5;
    const int bn = blockIdx.x * 128;
    const int bm = blockIdx.y * 128;

    // loader coordinates (threads 0..255)
    const int ar0 = tid >> 2, ac8 = (tid & 3) * 8;
    const int br0 = tid >> 4, bc8 = (tid & 15) * 8;

    auto issue = [&](int c, int buf) {
        if (tid < 256) {
            const int kc = c * 32;
            char* base = dsm + buf * BUF_BYTES;
            #pragma unroll
            for (int i = 0; i < 2; i++) {
                int row = ar0 + i * 64;
                uint32_t dh = smem_u32(base + (row * 40 + ac8) * 2);
                uint32_t dl = smem_u32(base + 10240 + (row * 40 + ac8) * 2);
                cp16(dh, Ahi + (size_t)(bm + row) * K + kc + ac8);
                cp16(dl, Alo + (size_t)(bm + row) * K + kc + ac8);
            }
            #pragma unroll
            for (int i = 0; i < 2; i++) {
                int row = br0 + i * 16;
                uint32_t dh = smem_u32(base + 20480 + (row * 136 + bc8) * 2);
                uint32_t dl = smem_u32(base + 29184 + (row * 136 + bc8) * 2);
                cp16(dh, Bhi + (size_t)(kc + row) * N + bn + bc8);
                cp16(dl, Blo + (size_t)(kc + row) * N + bn + bc8);
            }
            CP_COMMIT();
        }
    };

    issue(0, 0);
    if (tid < 256) {
        int row = tid >> 4, c8 = (tid & 15) * 8;
        float4 v0 = *(const float4*)(bias + bn + c8);
        float4 v1 = *(const float4*)(bias + bn + c8 + 4);
        *(float4*)&bias_s[row * 128 + c8]     = v0;
        *(float4*)&bias_s[row * 128 + c8 + 4] = v1;
    }
    __syncthreads();

    const int NC = K / 32;

    if (wid < 8) {
        // ------------------- wmma path: rows 0..111, n-tile = wid*16 -------
        const int nw = wid * 16;
        wmma::fragment<wmma::accumulator, 16, 16, 16, float> acc[7];
        #pragma unroll
        for (int i = 0; i < 7; i++)
            wmma::load_matrix_sync(acc[i], &bias_s[nw], 128, wmma::mem_row_major);

        for (int c = 0; c < NC; c++) {
            const int cur = c & 1;
            if (c + 1 < NC) { issue(c + 1, cur ^ 1); CP_WAIT1(); }
            else            { CP_WAIT0(); }
            __syncthreads();

            char* base = dsm + cur * BUF_BYTES;
            bf16* As_hi = (bf16*)(base);
            bf16* As_lo = (bf16*)(base + 10240);
            bf16* Bs_hi = (bf16*)(base + 20480);
            bf16* Bs_lo = (bf16*)(base + 29184);

            #pragma unroll
            for (int kk = 0; kk < 32; kk += 16) {
                wmma::fragment<wmma::matrix_b, 16, 16, 16, bf16, wmma::row_major> bh, bl;
                wmma::load_matrix_sync(bh, &Bs_hi[kk * 136 + nw], 136);
                wmma::load_matrix_sync(bl, &Bs_lo[kk * 136 + nw], 136);
                #pragma unroll
                for (int i = 0; i < 7; i++) {
                    wmma::fragment<wmma::matrix_a, 16, 16, 16, bf16, wmma::row_major> a_hi, a_lo;
                    wmma::load_matrix_sync(a_hi, &As_hi[(i * 16) * 40 + kk], 40);
                    wmma::load_matrix_sync(a_lo, &As_lo[(i * 16) * 40 + kk], 40);
                    wmma::mma_sync(acc[i], a_hi, bh, acc[i]);
                    wmma::mma_sync(acc[i], a_hi, bl, acc[i]);
                    wmma::mma_sync(acc[i], a_lo, bh, acc[i]);
                }
            }
            __syncthreads();
        }

        if (MODE == 0) {
            #pragma unroll
            for (int i = 0; i < 7; i++)
                wmma::store_matrix_sync(
                    Cf + (size_t)(bm + i * 16) * N + bn + nw,
                    acc[i], N, wmma::mem_row_major);
        } else {
            float* stage = (float*)dsm;
            #pragma unroll
            for (int i = 0; i < 7; i++) {
                #pragma unroll
                for (int e = 0; e < acc[i].num_elements; e++)
                    acc[i].x[e] = fmaxf(acc[i].x[e], 0.f);
                wmma::store_matrix_sync(&stage[(i * 16) * 128 + nw],
                                        acc[i], 128, wmma::mem_row_major);
            }
        }
    } else {
        // ------------------- scalar path: rows 112..127 --------------------
        const int gid  = tid - 256;              // 0..63
        const int rloc = (gid >> 3) * 2;         // 0,2,..,14 (local row in 16)
        const int scol = (gid & 7) * 16;         // 0..112

        ull acc2[2][8];
        #pragma unroll
        for (int r = 0; r < 2; r++)
            #pragma unroll
            for (int j = 0; j < 8; j++) acc2[r][j] = 0ull;

        for (int c = 0; c < NC; c++) {
            const int cur = c & 1;
            if (c + 1 < NC) { CP_WAIT1(); } else { CP_WAIT0(); }
            __syncthreads();

            char* base = dsm + cur * BUF_BYTES;
            const unsigned short* As_hi = (const unsigned short*)(base);
            const unsigned short* As_lo = (const unsigned short*)(base + 10240);
            const uint32_t* Bs_hi32 = (const uint32_t*)(base + 20480);
            const uint32_t* Bs_lo32 = (const uint32_t*)(base + 29184);

            // reconstruct Asf (rows 112..127 -> local 0..15) : 512 vals
            #pragma unroll
            for (int t = 0; t < 8; t++) {
                int idx = gid * 8 + t;
                int r = idx >> 5, k = idx & 31;
                float v = bf2f(As_hi[(112 + r) * 40 + k])
                        + bf2f(As_lo[(112 + r) * 40 + k]);
                Asf[r * 33 + k] = v;
            }
            // reconstruct Bsf: 32kk x 128 cols as packed pairs (2048 pairs)
            #pragma unroll
            for (int t = 0; t < 32; t++) {
                int f = t * 64 + gid;            // pair index
                int kk = f >> 6, cp = (f & 63) * 2;
                uint32_t uh = Bs_hi32[(kk * 136 + cp) >> 1];
                uint32_t ul = Bs_lo32[(kk * 136 + cp) >> 1];
                float b0 = __uint_as_float(uh << 16) + __uint_as_float(ul << 16);
                float b1 = __uint_as_float(uh & 0xffff0000u)
                         + __uint_as_float(ul & 0xffff0000u);
                float2 bb; bb.x = b0; bb.y = b1;
                *(float2*)&Bsf[kk * 132 + cp] = bb;
            }
            asm volatile("bar.sync 1, 64;" ::: "memory");

            #pragma unroll 4
            for (int kk = 0; kk < 32; kk++) {
                float a0 = Asf[rloc * 33 + kk];
                float a1 = Asf[(rloc + 1) * 33 + kk];
                ull a0d = pack_dup(__float_as_uint(a0));
                ull a1d = pack_dup(__float_as_uint(a1));
                const ull* bp = (const ull*)&Bsf[kk * 132 + scol];
                #pragma unroll
                for (int j = 0; j < 8; j++) {
                    ull b = bp[j];
                    ffma2(acc2[0][j], a0d, b);
                    ffma2(acc2[1][j], a1d, b);
                }
            }
            __syncthreads();
        }

        // scalar epilogue
        const int grow = 112 + rloc;
        #pragma unroll
        for (int r = 0; r < 2; r++) {
            float vals[16];
            #pragma unroll
            for (int j = 0; j < 8; j++) {
                vals[2 * j]     = __uint_as_float((unsigned)(acc2[r][j]));
                vals[2 * j + 1] = __uint_as_float((unsigned)(acc2[r][j] >> 32));
            }
            #pragma unroll
            for (int e = 0; e < 16; e++) {
                vals[e] = vals[e] + bias_s[scol + e];
                if (MODE == 1) vals[e] = fmaxf(vals[e], 0.f);
            }
            if (MODE == 0) {
                float* cp = Cf + (size_t)(bm + grow + r) * N + bn + scol;
                #pragma unroll
                for (int q = 0; q < 16; q += 4)
                    *(float4*)(cp + q) = *(const float4*)&vals[q];
            } else {
                float* stage = (float*)dsm;
                #pragma unroll
                for (int q = 0; q < 16; q += 4)
                    *(float4*)&stage[(grow + r) * 128 + scol + q] =
                        *(const float4*)&vals[q];
            }
        }
    }

    if (MODE == 1) {
        __syncthreads();
        float* stage = (float*)dsm;
        for (int f = tid; f < 4096; f += 320) {
            int row = f >> 5, c4 = (f & 31) * 4;
            float4 v = *(const float4*)&stage[row * 128 + c4];
            float vv[4] = {v.x, v.y, v.z, v.w};
            ull hp = 0, lp = 0;
            #pragma unroll
            for (int e = 0; e < 4; e++) {
                bf16 h = __float2bfloat16_rn(vv[e]);
                bf16 l = __float2bfloat16_rn(vv[e] - __bfloat162float(h));
                hp |= (ull)__bfloat16_as_ushort(h) << (16 * e);
                lp |= (ull)__bfloat16_as_ushort(l) << (16 * e);
            }
            size_t off = (size_t)(bm + row) * N + bn + c4;
            *(ull*)(Chi + off) = hp;
            *(ull*)(Clo + off) = lp;
        }
    }
}

// ---------------------------------------------------------------------------
// Encoder SGEMM via FFMA2 (bit-exact per-element k-ascending FMA). FROZEN.
// ---------------------------------------------------------------------------
template<bool RELU>
__global__ __launch_bounds__(256, 2)
void sgemm(const float* __restrict__ A, const float* __restrict__ W,
           const float* __restrict__ bias, float* __restrict__ C,
           int M, int N, int K)
{
    __shared__ __align__(16) float As[2][8][128];
    __shared__ __align__(16) float Bs[2][8][128];

    const int tid = threadIdx.x;
    const int bm = blockIdx.y * 128;
    const int bn = blockIdx.x * 128;

    const int arow = tid >> 1;
    const int acol = (tid & 1) * 4;
    const int wrow = tid >> 5;
    const int wcol = (tid & 31) * 4;

    const int tx = tid & 15;
    const int ty = tid >> 4;

    ull acc2[4][8];
    #pragma unroll
    for (int i = 0; i < 4; i++)
        #pragma unroll
        for (int j = 0; j < 8; j++) acc2[i][j] = 0ull;

    const float* Aptr = A + (size_t)(bm + arow) * K + acol;
    const float* Wptr = W + (size_t)wrow * N + bn + wcol;

    const int nt = K >> 3;

    float4 av = *(const float4*)(Aptr);
    float4 wv = *(const float4*)(Wptr);
    As[0][acol + 0][arow] = av.x;
    As[0][acol + 1][arow] = av.y;
    As[0][acol + 2][arow] = av.z;
    As[0][acol + 3][arow] = av.w;
    *(float4*)&Bs[0][wrow][wcol] = wv;
    __syncthreads();

    for (int t = 0; t < nt; t++) {
        const int cur = t & 1;
        if (t + 1 < nt) {
            av = *(const float4*)(Aptr + (t + 1) * 8);
            wv = *(const float4*)(Wptr + (size_t)(t + 1) * 8 * N);
        }

        #pragma unroll
        for (int kk = 0; kk < 8; kk++) {
            ull a2[4];
            const ull* ap = (const ull*)&As[cur][kk][ty * 8];
            a2[0] = ap[0]; a2[1] = ap[1]; a2[2] = ap[2]; a2[3] = ap[3];

            uint4 bv0 = *(const uint4*)&Bs[cur][kk][tx * 8];
            uint4 bv1 = *(const uint4*)&Bs[cur][kk][tx * 8 + 4];
            ull bd[8];
            bd[0] = pack_dup(bv0.x); bd[1] = pack_dup(bv0.y);
            bd[2] = pack_dup(bv0.z); bd[3] = pack_dup(bv0.w);
            bd[4] = pack_dup(bv1.x); bd[5] = pack_dup(bv1.y);
            bd[6] = pack_dup(bv1.z); bd[7] = pack_dup(bv1.w);

            #pragma unroll
            for (int i = 0; i < 4; i++)
                #pragma unroll
                for (int j = 0; j < 8; j++)
                    ffma2(acc2[i][j], a2[i], bd[j]);
        }

        if (t + 1 < nt) {
            const int nxt = cur ^ 1;
            As[nxt][acol + 0][arow] = av.x;
            As[nxt][acol + 1][arow] = av.y;
            As[nxt][acol + 2][arow] = av.z;
            As[nxt][acol + 3][arow] = av.w;
            *(float4*)&Bs[nxt][wrow][wcol] = wv;
            __syncthreads();
        }
    }

    float bb[8];
    *(float4*)&bb[0] = *(const float4*)(bias + bn + tx * 8);
    *(float4*)&bb[4] = *(const float4*)(bias + bn + tx * 8 + 4);

    #pragma unroll
    for (int i2 = 0; i2 < 4; i2++) {
        float lo[8], hi[8];
        #pragma unroll
        for (int j = 0; j < 8; j++) {
            lo[j] = __uint_as_float((unsigned)(acc2[i2][j]));
            hi[j] = __uint_as_float((unsigned)(acc2[i2][j] >> 32));
        }
        #pragma unroll
        for (int half = 0; half < 2; half++) {
            const float* accr = half ? hi : lo;
            size_t row = (size_t)(bm + ty * 8 + i2 * 2 + half);
            float* cp = C + row * N + bn + tx * 8;
            float4 v0, v1;
            v0.x = __fadd_rn(accr[0], bb[0]); v0.y = __fadd_rn(accr[1], bb[1]);
            v0.z = __fadd_rn(accr[2], bb[2]); v0.w = __fadd_rn(accr[3], bb[3]);
            v1.x = __fadd_rn(accr[4], bb[4]); v1.y = __fadd_rn(accr[5], bb[5]);
            v1.z = __fadd_rn(accr[6], bb[6]); v1.w = __fadd_rn(accr[7], bb[7]);
            if (RELU) {
                v0.x = fmaxf(v0.x, 0.f); v0.y = fmaxf(v0.y, 0.f);
                v0.z = fmaxf(v0.z, 0.f); v0.w = fmaxf(v0.w, 0.f);
                v1.x = fmaxf(v1.x, 0.f); v1.y = fmaxf(v1.y, 0.f);
                v1.z = fmaxf(v1.z, 0.f); v1.w = fmaxf(v1.w, 0.f);
            }
            *(float4*)cp = v0;
            *(float4*)(cp + 4) = v1;
        }
    }
}

// ---------------------------------------------------------------------------
// VQ kernel: FROZEN per-element numerics, FFMA2-packed; emits zq + hi/lo.
// ---------------------------------------------------------------------------
__global__ __launch_bounds__(256)
void vq_kernel(const float* __restrict__ Z, const float* __restrict__ emb,
               const float* __restrict__ Bk,
               const bf16* __restrict__ ehi, const bf16* __restrict__ elo,
               float* __restrict__ zq, bf16* __restrict__ zqhi,
               bf16* __restrict__ zqlo, float* __restrict__ idx_out)
{
    __shared__ float z_s[32][DDIM];
    __shared__ __align__(16) float e_s[DDIM][128];
    __shared__ float bk_s[128];

    const int tid  = threadIdx.x;
    const int lane = tid & 31;
    const int warp = tid >> 5;
    const size_t row0 = (size_t)blockIdx.x * 32;
    const int r0 = warp * 4;

    {
        const float4* zg = (const float4*)(Z + row0 * DDIM);
        float4* zs = (float4*)z_s;
        zs[tid]       = zg[tid];
        zs[tid + 256] = zg[tid + 256];
    }
    __syncthreads();

    float Ar[4];
    #pragma unroll
    for (int rr = 0; rr < 4; rr++) {
        const float* zp = z_s[r0 + rr];
        float z0 = zp[lane], z1 = zp[lane + 32];
        float p = __fadd_rn(__fmul_rn(z0, z0), __fmul_rn(z1, z1));
        #pragma unroll
        for (int off = 16; off > 0; off >>= 1)
            p = __fadd_rn(p, __shfl_down_sync(0xffffffffu, p, off));
        Ar[rr] = __shfl_sync(0xffffffffu, p, 0);
    }

    float best_d[4];
    int   best_k[4];
    #pragma unroll
    for (int r = 0; r < 4; r++) { best_d[r] = 3.4e38f; best_k[r] = 0; }

    for (int c0 = 0; c0 < KCODES; c0 += 128) {
        __syncthreads();
        {
            int kk = tid >> 1;
            int d0 = (tid & 1) * 32;
            const float* ep = emb + (size_t)(c0 + kk) * DDIM + d0;
            #pragma unroll
            for (int i = 0; i < 32; i += 4) {
                float4 v = *(const float4*)(ep + i);
                e_s[d0 + i + 0][kk] = v.x;
                e_s[d0 + i + 1][kk] = v.y;
                e_s[d0 + i + 2][kk] = v.z;
                e_s[d0 + i + 3][kk] = v.w;
            }
            if (tid < 128) bk_s[tid] = Bk[c0 + tid];
        }
        __syncthreads();

        ull accL[4][2], accH[4][2];
        #pragma unroll
        for (int r = 0; r < 4; r++)
            #pragma unroll
            for (int s = 0; s < 2; s++) { accL[r][s] = 0ull; accH[r][s] = 0ull; }

        #pragma unroll
        for (int d4 = 0; d4 < DDIM / 2; d4 += 4) {
            float4 zr[4];
            #pragma unroll
            for (int r = 0; r < 4; r++)
                zr[r] = *(const float4*)&z_s[r0 + r][d4];
            #pragma unroll
            for (int dd = 0; dd < 4; dd++) {
                int d = d4 + dd;
                ull ev0 = *(const ull*)&e_s[d][2 * lane];
                ull ev1 = *(const ull*)&e_s[d][64 + 2 * lane];
                #pragma unroll
                for (int r = 0; r < 4; r++) {
                    float zf = (dd == 0) ? zr[r].x : (dd == 1) ? zr[r].y
                             : (dd == 2) ? zr[r].z : zr[r].w;
                    ull zd = pack_dup(__float_as_uint(zf));
                    ffma2(accL[r][0], zd, ev0);
                    ffma2(accL[r][1], zd, ev1);
                }
            }
        }
        #pragma unroll
        for (int d4 = DDIM / 2; d4 < DDIM; d4 += 4) {
            float4 zr[4];
            #pragma unroll
            for (int r = 0; r < 4; r++)
                zr[r] = *(const float4*)&z_s[r0 + r][d4];
            #pragma unroll
            for (int dd = 0; dd < 4; dd++) {
                int d = d4 + dd;
                ull ev0 = *(const ull*)&e_s[d][2 * lane];
                ull ev1 = *(const ull*)&e_s[d][64 + 2 * lane];
                #pragma unroll
                for (int r = 0; r < 4; r++) {
                    float zf = (dd == 0) ? zr[r].x : (dd == 1) ? zr[r].y
                             : (dd == 2) ? zr[r].z : zr[r].w;
                    ull zd = pack_dup(__float_as_uint(zf));
                    ffma2(accH[r][0], zd, ev0);
                    ffma2(accH[r][1], zd, ev1);
                }
            }
        }

        #pragma unroll
        for (int r = 0; r < 4; r++) {
            #pragma unroll
            for (int s = 0; s < 2; s++) {
                #pragma unroll
                for (int j = 0; j < 2; j++) {
                    float eL = __uint_as_float(j == 0 ? (unsigned)accL[r][s]
                                                      : (unsigned)(accL[r][s] >> 32));
                    float eH = __uint_as_float(j == 0 ? (unsigned)accH[r][s]
                                                      : (unsigned)(accH[r][s] >> 32));
                    int kc = s * 64 + 2 * lane + j;
                    float E  = __fadd_rn(eL, eH);
                    float t  = __fadd_rn(Ar[r], bk_s[kc]);
                    float ds = __fadd_rn(t, -2.0f * E);
                    int k = c0 + kc;
                    if (ds < best_d[r]) { best_d[r] = ds; best_k[r] = k; }
                }
            }
        }
    }

    #pragma unroll
    for (int r = 0; r < 4; r++) {
        float bd = best_d[r];
        int   bk = best_k[r];
        #pragma unroll
        for (int off = 16; off > 0; off >>= 1) {
            float od = __shfl_down_sync(0xffffffffu, bd, off);
            int   ok = __shfl_down_sync(0xffffffffu, bk, off);
            if (od < bd || (od == bd && ok < bk)) { bd = od; bk = ok; }
        }
        bk = __shfl_sync(0xffffffffu, bk, 0);

        size_t grow = row0 + (size_t)warp * 4 + r;
        zq[grow * DDIM + lane]      = emb[(size_t)bk * DDIM + lane];
        zq[grow * DDIM + 32 + lane] = emb[(size_t)bk * DDIM + 32 + lane];
        zqhi[grow * DDIM + lane]      = ehi[bk * DDIM + lane];
        zqhi[grow * DDIM + 32 + lane] = ehi[bk * DDIM + 32 + lane];
        zqlo[grow * DDIM + lane]      = elo[bk * DDIM + lane];
        zqlo[grow * DDIM + 32 + lane] = elo[bk * DDIM + 32 + lane];
        if (lane == 0) idx_out[grow] = (float)bk;
    }
}

// ---------------------------------------------------------------------------
extern "C" void kernel_launch(void* const* d_in, const int* in_sizes, int n_in,
                              void* d_out, int out_size)
{
    const float* x   = (const float*)d_in[0];
    const float* W1  = (const float*)d_in[1];
    const float* b1  = (const float*)d_in[2];
    const float* W2  = (const float*)d_in[3];
    const float* b2  = (const float*)d_in[4];
    const float* emb = (const float*)d_in[5];
    const float* W3  = (const float*)d_in[6];
    const float* b3  = (const float*)d_in[7];
    const float* W4  = (const float*)d_in[8];
    const float* b4  = (const float*)d_in[9];

    float* out     = (float*)d_out;
    float* x_recon = out;
    float* z       = out + (size_t)B_ * IN_DIM;
    float* zq      = z   + (size_t)B_ * (LLAT * DDIM);
    float* idxf    = zq  + (size_t)B_ * (LLAT * DDIM);

    float *h, *Bk;
    bf16 *zqhi, *zqlo, *h2hi, *h2lo, *w3hi, *w3lo, *w4hi, *w4lo, *ehi, *elo;
    cudaGetSymbolAddress((void**)&h,    g_h);
    cudaGetSymbolAddress((void**)&Bk,   g_Bk);
    cudaGetSymbolAddress((void**)&zqhi, g_zqhi);
    cudaGetSymbolAddress((void**)&zqlo, g_zqlo);
    cudaGetSymbolAddress((void**)&h2hi, g_h2hi);
    cudaGetSymbolAddress((void**)&h2lo, g_h2lo);
    cudaGetSymbolAddress((void**)&w3hi, g_w3hi);
    cudaGetSymbolAddress((void**)&w3lo, g_w3lo);
    cudaGetSymbolAddress((void**)&w4hi, g_w4hi);
    cudaGetSymbolAddress((void**)&w4lo, g_w4lo);
    cudaGetSymbolAddress((void**)&ehi,  g_ehi);
    cudaGetSymbolAddress((void**)&elo,  g_elo);

    static int attr_set = 0;
    if (!attr_set) {
        cudaFuncSetAttribute(gemm_wmma<0>,
            cudaFuncAttributeMaxDynamicSharedMemorySize, SM_TOTAL);
        cudaFuncSetAttribute(gemm_wmma<1>,
            cudaFuncAttributeMaxDynamicSharedMemorySize, SM_TOTAL);
        attr_set = 1;
    }

    // prep (input-only dependent)
    bk_kernel<<<(KCODES * 32 + 255) / 256, 256>>>(emb, Bk);
    splitf<<<(KCODES * DDIM) / 1024, 256>>>(emb, ehi, elo);
    splitf<<<((size_t)HID * HID) / 1024, 256>>>(W3, w3hi, w3lo);
    splitf<<<((size_t)HID * IN_DIM) / 1024, 256>>>(W4, w4hi, w4lo);

    // encoder (bit-frozen)
    sgemm<true ><<<dim3(HID / 128, B_ / 128), 256>>>(x, W1, b1, h, B_, HID, IN_DIM);
    sgemm<false><<<dim3(HID / 128, B_ / 128), 256>>>(h, W2, b2, z, B_, HID, HID);
    vq_kernel<<<(B_ * LLAT) / 32, 256>>>(z, emb, Bk, ehi, elo, zq, zqhi, zqlo, idxf);

    // decoder (hybrid-warp wmma bf16x3 + FFMA2 rows, cp.async double-buffered)
    gemm_wmma<1><<<dim3(HID / 128, B_ / 128), 320, SM_TOTAL>>>(
        zqhi, zqlo, w3hi, w3lo, b3, nullptr, h2hi, h2lo, HID, HID);
    gemm_wmma<0><<<dim3(IN_DIM / 128, B_ / 128), 320, SM_TOTAL>>>(
        h2hi, h2lo, w4hi, w4lo, b4, x_recon, nullptr, nullptr, IN_DIM, HID);
}

// round 17
// speedup vs baseline: 1.6274x; 1.6274x over previous
#include <cuda_runtime.h>
#include <cuda_bf16.h>
#include <mma.h>
#include <cstddef>
#include <cstdint>

using namespace nvcuda;

// ---------------------------------------------------------------------------
// VQ-VAE forward. NUMERICS:
//  - Encoder GEMMs 1-2 + VQ: BIT-FROZEN (argmin must never flip).
//  - Decoder: GEMM3/GEMM4 wmma bf16x3, cp.async double-buffered (R15 form,
//    with guaranteed 2 CTAs/SM via launch_bounds).
// ---------------------------------------------------------------------------

#define B_      8192
#define IN_DIM  1024
#define HID     2048
#define KCODES  512
#define DDIM    64
#define LLAT    32

typedef unsigned long long ull;
typedef __nv_bfloat16 bf16;

__device__ float g_h [(size_t)B_ * HID];      // G1 output (fp32, frozen)
__device__ float g_Bk[KCODES];
__device__ bf16 g_zqhi[(size_t)B_ * HID];
__device__ bf16 g_zqlo[(size_t)B_ * HID];
__device__ bf16 g_h2hi[(size_t)B_ * HID];
__device__ bf16 g_h2lo[(size_t)B_ * HID];
__device__ bf16 g_w3hi[(size_t)HID * HID];
__device__ bf16 g_w3lo[(size_t)HID * HID];
__device__ bf16 g_w4hi[(size_t)HID * IN_DIM];
__device__ bf16 g_w4lo[(size_t)HID * IN_DIM];
__device__ bf16 g_ehi[KCODES * DDIM];
__device__ bf16 g_elo[KCODES * DDIM];

// ---- packed f32x2 helpers ---------------------------------------------------
__device__ __forceinline__ ull pack_dup(unsigned u) {
    ull r;
    asm("mov.b64 %0, {%1, %1};" : "=l"(r) : "r"(u));
    return r;
}
__device__ __forceinline__ void ffma2(ull& acc, ull a, ull b) {
    asm("fma.rn.f32x2 %0, %1, %2, %0;" : "+l"(acc) : "l"(a), "l"(b));
}

// ---- cp.async helpers -------------------------------------------------------
__device__ __forceinline__ uint32_t smem_u32(const void* p) {
    uint32_t a;
    asm("{ .reg .u64 t; cvta.to.shared.u64 t, %1; cvt.u32.u64 %0, t; }"
        : "=r"(a) : "l"(p));
    return a;
}
__device__ __forceinline__ void cp16(uint32_t dst, const void* src) {
    asm volatile("cp.async.cg.shared.global [%0], [%1], 16;"
                 :: "r"(dst), "l"(src) : "memory");
}
#define CP_COMMIT() asm volatile("cp.async.commit_group;" ::: "memory")
#define CP_WAIT1()  asm volatile("cp.async.wait_group 1;" ::: "memory")
#define CP_WAIT0()  asm volatile("cp.async.wait_group 0;" ::: "memory")

// ---------------------------------------------------------------------------
__global__ void bk_kernel(const float* __restrict__ emb, float* __restrict__ Bk)
{
    int gwarp = (blockIdx.x * blockDim.x + threadIdx.x) >> 5;
    int lane  = threadIdx.x & 31;
    if (gwarp < KCODES) {
        const float* e = emb + (size_t)gwarp * DDIM;
        float e0 = e[2 * lane], e1 = e[2 * lane + 1];
        float p = __fadd_rn(__fmul_rn(e0, e0), __fmul_rn(e1, e1));
        #pragma unroll
        for (int off = 16; off > 0; off >>= 1)
            p = __fadd_rn(p, __shfl_down_sync(0xffffffffu, p, off));
        if (lane == 0) Bk[gwarp] = p;
    }
}

// ---------------------------------------------------------------------------
__global__ __launch_bounds__(256)
void splitf(const float* __restrict__ src, bf16* __restrict__ hi,
            bf16* __restrict__ lo)
{
    size_t i = ((size_t)blockIdx.x * 256 + threadIdx.x) * 4;
    float4 v = *(const float4*)(src + i);
    float vv[4] = {v.x, v.y, v.z, v.w};
    ull hp = 0, lp = 0;
    #pragma unroll
    for (int e = 0; e < 4; e++) {
        bf16 h = __float2bfloat16_rn(vv[e]);
        bf16 l = __float2bfloat16_rn(vv[e] - __bfloat162float(h));
        hp |= (ull)__bfloat16_as_ushort(h) << (16 * e);
        lp |= (ull)__bfloat16_as_ushort(l) << (16 * e);
    }
    *(ull*)(hi + i) = hp;
    *(ull*)(lo + i) = lp;
}

// ---------------------------------------------------------------------------
// wmma bf16x3 GEMM, cp.async double-buffered (R15-proven).
// MODE 0: C fp32, no relu (G4).   MODE 1: relu, bf16 hi/lo out (G3).
// smem: 2 x 37888 (buffers) + 8192 (bias) = 83968 dynamic -> 2 CTAs/SM.
// ---------------------------------------------------------------------------
#define BUF_BYTES 37888
#define SM_BIAS   75776
#define SM_TOTAL  83968

template<int MODE>
__global__ __launch_bounds__(256, 2)
void gemm_wmma(const bf16* __restrict__ Ahi, const bf16* __restrict__ Alo,
               const bf16* __restrict__ Bhi, const bf16* __restrict__ Blo,
               const float* __restrict__ bias, float* __restrict__ Cf,
               bf16* __restrict__ Chi, bf16* __restrict__ Clo,
               int N, int K)
{
    extern __shared__ __align__(16) char dsm[];
    float* bias_s = (float*)(dsm + SM_BIAS);

    const int tid = threadIdx.x;
    const int wid = tid >> 5;
    const int bn = blockIdx.x * 128;
    const int bm = blockIdx.y * 128;
    const int mw = (wid & 1) * 64;
    const int nw = (wid >> 1) * 32;

    const int ar0 = tid >> 2, ac8 = (tid & 3) * 8;    // A: 2 iters of 64 rows
    const int br0 = tid >> 4, bc8 = (tid & 15) * 8;   // B: 2 iters of 16 rows

    auto issue = [&](int c, int buf) {
        const int kc = c * 32;
        char* base = dsm + buf * BUF_BYTES;
        #pragma unroll
        for (int i = 0; i < 2; i++) {
            int row = ar0 + i * 64;
            uint32_t dh = smem_u32(base + (row * 40 + ac8) * 2);
            uint32_t dl = smem_u32(base + 10240 + (row * 40 + ac8) * 2);
            cp16(dh, Ahi + (size_t)(bm + row) * K + kc + ac8);
            cp16(dl, Alo + (size_t)(bm + row) * K + kc + ac8);
        }
        #pragma unroll
        for (int i = 0; i < 2; i++) {
            int row = br0 + i * 16;
            uint32_t dh = smem_u32(base + 20480 + (row * 136 + bc8) * 2);
            uint32_t dl = smem_u32(base + 29184 + (row * 136 + bc8) * 2);
            cp16(dh, Bhi + (size_t)(kc + row) * N + bn + bc8);
            cp16(dl, Blo + (size_t)(kc + row) * N + bn + bc8);
        }
        CP_COMMIT();
    };

    issue(0, 0);
    {
        int row = tid >> 4, c8 = (tid & 15) * 8;
        float4 v0 = *(const float4*)(bias + bn + c8);
        float4 v1 = *(const float4*)(bias + bn + c8 + 4);
        *(float4*)&bias_s[row * 128 + c8]     = v0;
        *(float4*)&bias_s[row * 128 + c8 + 4] = v1;
    }
    __syncthreads();

    wmma::fragment<wmma::accumulator, 16, 16, 16, float> acc[4][2];
    #pragma unroll
    for (int i = 0; i < 4; i++)
        #pragma unroll
        for (int j = 0; j < 2; j++)
            wmma::load_matrix_sync(acc[i][j], &bias_s[nw + j * 16], 128,
                                   wmma::mem_row_major);

    const int NC = K / 32;
    for (int c = 0; c < NC; c++) {
        const int cur = c & 1;
        if (c + 1 < NC) { issue(c + 1, cur ^ 1); CP_WAIT1(); }
        else            { CP_WAIT0(); }
        __syncthreads();

        char* base = dsm + cur * BUF_BYTES;
        bf16* As_hi = (bf16*)(base);
        bf16* As_lo = (bf16*)(base + 10240);
        bf16* Bs_hi = (bf16*)(base + 20480);
        bf16* Bs_lo = (bf16*)(base + 29184);

        #pragma unroll
        for (int kk = 0; kk < 32; kk += 16) {
            wmma::fragment<wmma::matrix_b, 16, 16, 16, bf16, wmma::row_major> bh[2], bl[2];
            #pragma unroll
            for (int j = 0; j < 2; j++) {
                wmma::load_matrix_sync(bh[j], &Bs_hi[kk * 136 + nw + j * 16], 136);
                wmma::load_matrix_sync(bl[j], &Bs_lo[kk * 136 + nw + j * 16], 136);
            }
            #pragma unroll
            for (int i = 0; i < 4; i++) {
                wmma::fragment<wmma::matrix_a, 16, 16, 16, bf16, wmma::row_major> a_hi, a_lo;
                wmma::load_matrix_sync(a_hi, &As_hi[(mw + i * 16) * 40 + kk], 40);
                wmma::load_matrix_sync(a_lo, &As_lo[(mw + i * 16) * 40 + kk], 40);
                #pragma unroll
                for (int j = 0; j < 2; j++) {
                    wmma::mma_sync(acc[i][j], a_hi, bh[j], acc[i][j]);
                    wmma::mma_sync(acc[i][j], a_hi, bl[j], acc[i][j]);
                    wmma::mma_sync(acc[i][j], a_lo, bh[j], acc[i][j]);
                }
            }
        }
        __syncthreads();
    }

    if (MODE == 0) {
        #pragma unroll
        for (int i = 0; i < 4; i++)
            #pragma unroll
            for (int j = 0; j < 2; j++)
                wmma::store_matrix_sync(
                    Cf + (size_t)(bm + mw + i * 16) * N + bn + nw + j * 16,
                    acc[i][j], N, wmma::mem_row_major);
    } else {
        float* stage = (float*)dsm;   // 128 x 128 fp32 (buffers dead)
        #pragma unroll
        for (int i = 0; i < 4; i++)
            #pragma unroll
            for (int j = 0; j < 2; j++) {
                #pragma unroll
                for (int e = 0; e < acc[i][j].num_elements; e++)
                    acc[i][j].x[e] = fmaxf(acc[i][j].x[e], 0.f);
                wmma::store_matrix_sync(
                    &stage[(mw + i * 16) * 128 + nw + j * 16],
                    acc[i][j], 128, wmma::mem_row_major);
            }
        __syncthreads();
        #pragma unroll
        for (int ii = 0; ii < 16; ii++) {
            int f = ii * 256 + tid;
            int row = f >> 5, c4 = (f & 31) * 4;
            float4 v = *(const float4*)&stage[row * 128 + c4];
            float vv[4] = {v.x, v.y, v.z, v.w};
            ull hp = 0, lp = 0;
            #pragma unroll
            for (int e = 0; e < 4; e++) {
                bf16 h = __float2bfloat16_rn(vv[e]);
                bf16 l = __float2bfloat16_rn(vv[e] - __bfloat162float(h));
                hp |= (ull)__bfloat16_as_ushort(h) << (16 * e);
                lp |= (ull)__bfloat16_as_ushort(l) << (16 * e);
            }
            size_t off = (size_t)(bm + row) * N + bn + c4;
            *(ull*)(Chi + off) = hp;
            *(ull*)(Clo + off) = lp;
        }
    }
}

// ---------------------------------------------------------------------------
// Encoder SGEMM via FFMA2 (bit-exact per-element k-ascending FMA). FROZEN.
// ---------------------------------------------------------------------------
template<bool RELU>
__global__ __launch_bounds__(256, 2)
void sgemm(const float* __restrict__ A, const float* __restrict__ W,
           const float* __restrict__ bias, float* __restrict__ C,
           int M, int N, int K)
{
    __shared__ __align__(16) float As[2][8][128];
    __shared__ __align__(16) float Bs[2][8][128];

    const int tid = threadIdx.x;
    const int bm = blockIdx.y * 128;
    const int bn = blockIdx.x * 128;

    const int arow = tid >> 1;
    const int acol = (tid & 1) * 4;
    const int wrow = tid >> 5;
    const int wcol = (tid & 31) * 4;

    const int tx = tid & 15;
    const int ty = tid >> 4;

    ull acc2[4][8];
    #pragma unroll
    for (int i = 0; i < 4; i++)
        #pragma unroll
        for (int j = 0; j < 8; j++) acc2[i][j] = 0ull;

    const float* Aptr = A + (size_t)(bm + arow) * K + acol;
    const float* Wptr = W + (size_t)wrow * N + bn + wcol;

    const int nt = K >> 3;

    float4 av = *(const float4*)(Aptr);
    float4 wv = *(const float4*)(Wptr);
    As[0][acol + 0][arow] = av.x;
    As[0][acol + 1][arow] = av.y;
    As[0][acol + 2][arow] = av.z;
    As[0][acol + 3][arow] = av.w;
    *(float4*)&Bs[0][wrow][wcol] = wv;
    __syncthreads();

    for (int t = 0; t < nt; t++) {
        const int cur = t & 1;
        if (t + 1 < nt) {
            av = *(const float4*)(Aptr + (t + 1) * 8);
            wv = *(const float4*)(Wptr + (size_t)(t + 1) * 8 * N);
        }

        #pragma unroll
        for (int kk = 0; kk < 8; kk++) {
            ull a2[4];
            const ull* ap = (const ull*)&As[cur][kk][ty * 8];
            a2[0] = ap[0]; a2[1] = ap[1]; a2[2] = ap[2]; a2[3] = ap[3];

            uint4 bv0 = *(const uint4*)&Bs[cur][kk][tx * 8];
            uint4 bv1 = *(const uint4*)&Bs[cur][kk][tx * 8 + 4];
            ull bd[8];
            bd[0] = pack_dup(bv0.x); bd[1] = pack_dup(bv0.y);
            bd[2] = pack_dup(bv0.z); bd[3] = pack_dup(bv0.w);
            bd[4] = pack_dup(bv1.x); bd[5] = pack_dup(bv1.y);
            bd[6] = pack_dup(bv1.z); bd[7] = pack_dup(bv1.w);

            #pragma unroll
            for (int i = 0; i < 4; i++)
                #pragma unroll
                for (int j = 0; j < 8; j++)
                    ffma2(acc2[i][j], a2[i], bd[j]);
        }

        if (t + 1 < nt) {
            const int nxt = cur ^ 1;
            As[nxt][acol + 0][arow] = av.x;
            As[nxt][acol + 1][arow] = av.y;
            As[nxt][acol + 2][arow] = av.z;
            As[nxt][acol + 3][arow] = av.w;
            *(float4*)&Bs[nxt][wrow][wcol] = wv;
            __syncthreads();
        }
    }

    float bb[8];
    *(float4*)&bb[0] = *(const float4*)(bias + bn + tx * 8);
    *(float4*)&bb[4] = *(const float4*)(bias + bn + tx * 8 + 4);

    #pragma unroll
    for (int i2 = 0; i2 < 4; i2++) {
        float lo[8], hi[8];
        #pragma unroll
        for (int j = 0; j < 8; j++) {
            lo[j] = __uint_as_float((unsigned)(acc2[i2][j]));
            hi[j] = __uint_as_float((unsigned)(acc2[i2][j] >> 32));
        }
        #pragma unroll
        for (int half = 0; half < 2; half++) {
            const float* accr = half ? hi : lo;
            size_t row = (size_t)(bm + ty * 8 + i2 * 2 + half);
            float* cp = C + row * N + bn + tx * 8;
            float4 v0, v1;
            v0.x = __fadd_rn(accr[0], bb[0]); v0.y = __fadd_rn(accr[1], bb[1]);
            v0.z = __fadd_rn(accr[2], bb[2]); v0.w = __fadd_rn(accr[3], bb[3]);
            v1.x = __fadd_rn(accr[4], bb[4]); v1.y = __fadd_rn(accr[5], bb[5]);
            v1.z = __fadd_rn(accr[6], bb[6]); v1.w = __fadd_rn(accr[7], bb[7]);
            if (RELU) {
                v0.x = fmaxf(v0.x, 0.f); v0.y = fmaxf(v0.y, 0.f);
                v0.z = fmaxf(v0.z, 0.f); v0.w = fmaxf(v0.w, 0.f);
                v1.x = fmaxf(v1.x, 0.f); v1.y = fmaxf(v1.y, 0.f);
                v1.z = fmaxf(v1.z, 0.f); v1.w = fmaxf(v1.w, 0.f);
            }
            *(float4*)cp = v0;
            *(float4*)(cp + 4) = v1;
        }
    }
}

// ---------------------------------------------------------------------------
// VQ kernel: FROZEN per-element numerics, FFMA2-packed; emits zq + hi/lo.
// ---------------------------------------------------------------------------
__global__ __launch_bounds__(256)
void vq_kernel(const float* __restrict__ Z, const float* __restrict__ emb,
               const float* __restrict__ Bk,
               const bf16* __restrict__ ehi, const bf16* __restrict__ elo,
               float* __restrict__ zq, bf16* __restrict__ zqhi,
               bf16* __restrict__ zqlo, float* __restrict__ idx_out)
{
    __shared__ float z_s[32][DDIM];
    __shared__ __align__(16) float e_s[DDIM][128];
    __shared__ float bk_s[128];

    const int tid  = threadIdx.x;
    const int lane = tid & 31;
    const int warp = tid >> 5;
    const size_t row0 = (size_t)blockIdx.x * 32;
    const int r0 = warp * 4;

    {
        const float4* zg = (const float4*)(Z + row0 * DDIM);
        float4* zs = (float4*)z_s;
        zs[tid]       = zg[tid];
        zs[tid + 256] = zg[tid + 256];
    }
    __syncthreads();

    float Ar[4];
    #pragma unroll
    for (int rr = 0; rr < 4; rr++) {
        const float* zp = z_s[r0 + rr];
        float z0 = zp[lane], z1 = zp[lane + 32];
        float p = __fadd_rn(__fmul_rn(z0, z0), __fmul_rn(z1, z1));
        #pragma unroll
        for (int off = 16; off > 0; off >>= 1)
            p = __fadd_rn(p, __shfl_down_sync(0xffffffffu, p, off));
        Ar[rr] = __shfl_sync(0xffffffffu, p, 0);
    }

    float best_d[4];
    int   best_k[4];
    #pragma unroll
    for (int r = 0; r < 4; r++) { best_d[r] = 3.4e38f; best_k[r] = 0; }

    for (int c0 = 0; c0 < KCODES; c0 += 128) {
        __syncthreads();
        {
            int kk = tid >> 1;
            int d0 = (tid & 1) * 32;
            const float* ep = emb + (size_t)(c0 + kk) * DDIM + d0;
            #pragma unroll
            for (int i = 0; i < 32; i += 4) {
                float4 v = *(const float4*)(ep + i);
                e_s[d0 + i + 0][kk] = v.x;
                e_s[d0 + i + 1][kk] = v.y;
                e_s[d0 + i + 2][kk] = v.z;
                e_s[d0 + i + 3][kk] = v.w;
            }
            if (tid < 128) bk_s[tid] = Bk[c0 + tid];
        }
        __syncthreads();

        ull accL[4][2], accH[4][2];
        #pragma unroll
        for (int r = 0; r < 4; r++)
            #pragma unroll
            for (int s = 0; s < 2; s++) { accL[r][s] = 0ull; accH[r][s] = 0ull; }

        #pragma unroll
        for (int d4 = 0; d4 < DDIM / 2; d4 += 4) {
            float4 zr[4];
            #pragma unroll
            for (int r = 0; r < 4; r++)
                zr[r] = *(const float4*)&z_s[r0 + r][d4];
            #pragma unroll
            for (int dd = 0; dd < 4; dd++) {
                int d = d4 + dd;
                ull ev0 = *(const ull*)&e_s[d][2 * lane];
                ull ev1 = *(const ull*)&e_s[d][64 + 2 * lane];
                #pragma unroll
                for (int r = 0; r < 4; r++) {
                    float zf = (dd == 0) ? zr[r].x : (dd == 1) ? zr[r].y
                             : (dd == 2) ? zr[r].z : zr[r].w;
                    ull zd = pack_dup(__float_as_uint(zf));
                    ffma2(accL[r][0], zd, ev0);
                    ffma2(accL[r][1], zd, ev1);
                }
            }
        }
        #pragma unroll
        for (int d4 = DDIM / 2; d4 < DDIM; d4 += 4) {
            float4 zr[4];
            #pragma unroll
            for (int r = 0; r < 4; r++)
                zr[r] = *(const float4*)&z_s[r0 + r][d4];
            #pragma unroll
            for (int dd = 0; dd < 4; dd++) {
                int d = d4 + dd;
                ull ev0 = *(const ull*)&e_s[d][2 * lane];
                ull ev1 = *(const ull*)&e_s[d][64 + 2 * lane];
                #pragma unroll
                for (int r = 0; r < 4; r++) {
                    float zf = (dd == 0) ? zr[r].x : (dd == 1) ? zr[r].y
                             : (dd == 2) ? zr[r].z : zr[r].w;
                    ull zd = pack_dup(__float_as_uint(zf));
                    ffma2(accH[r][0], zd, ev0);
                    ffma2(accH[r][1], zd, ev1);
                }
            }
        }

        #pragma unroll
        for (int r = 0; r < 4; r++) {
            #pragma unroll
            for (int s = 0; s < 2; s++) {
                #pragma unroll
                for (int j = 0; j < 2; j++) {
                    float eL = __uint_as_float(j == 0 ? (unsigned)accL[r][s]
                                                      : (unsigned)(accL[r][s] >> 32));
                    float eH = __uint_as_float(j == 0 ? (unsigned)accH[r][s]
                                                      : (unsigned)(accH[r][s] >> 32));
                    int kc = s * 64 + 2 * lane + j;
                    float E  = __fadd_rn(eL, eH);
                    float t  = __fadd_rn(Ar[r], bk_s[kc]);
                    float ds = __fadd_rn(t, -2.0f * E);
                    int k = c0 + kc;
                    if (ds < best_d[r]) { best_d[r] = ds; best_k[r] = k; }
                }
            }
        }
    }

    #pragma unroll
    for (int r = 0; r < 4; r++) {
        float bd = best_d[r];
        int   bk = best_k[r];
        #pragma unroll
        for (int off = 16; off > 0; off >>= 1) {
            float od = __shfl_down_sync(0xffffffffu, bd, off);
            int   ok = __shfl_down_sync(0xffffffffu, bk, off);
            if (od < bd || (od == bd && ok < bk)) { bd = od; bk = ok; }
        }
        bk = __shfl_sync(0xffffffffu, bk, 0);

        size_t grow = row0 + (size_t)warp * 4 + r;
        zq[grow * DDIM + lane]      = emb[(size_t)bk * DDIM + lane];
        zq[grow * DDIM + 32 + lane] = emb[(size_t)bk * DDIM + 32 + lane];
        zqhi[grow * DDIM + lane]      = ehi[bk * DDIM + lane];
        zqhi[grow * DDIM + 32 + lane] = ehi[bk * DDIM + 32 + lane];
        zqlo[grow * DDIM + lane]      = elo[bk * DDIM + lane];
        zqlo[grow * DDIM + 32 + lane] = elo[bk * DDIM + 32 + lane];
        if (lane == 0) idx_out[grow] = (float)bk;
    }
}

// ---------------------------------------------------------------------------
extern "C" void kernel_launch(void* const* d_in, const int* in_sizes, int n_in,
                              void* d_out, int out_size)
{
    const float* x   = (const float*)d_in[0];
    const float* W1  = (const float*)d_in[1];
    const float* b1  = (const float*)d_in[2];
    const float* W2  = (const float*)d_in[3];
    const float* b2  = (const float*)d_in[4];
    const float* emb = (const float*)d_in[5];
    const float* W3  = (const float*)d_in[6];
    const float* b3  = (const float*)d_in[7];
    const float* W4  = (const float*)d_in[8];
    const float* b4  = (const float*)d_in[9];

    float* out     = (float*)d_out;
    float* x_recon = out;
    float* z       = out + (size_t)B_ * IN_DIM;
    float* zq      = z   + (size_t)B_ * (LLAT * DDIM);
    float* idxf    = zq  + (size_t)B_ * (LLAT * DDIM);

    float *h, *Bk;
    bf16 *zqhi, *zqlo, *h2hi, *h2lo, *w3hi, *w3lo, *w4hi, *w4lo, *ehi, *elo;
    cudaGetSymbolAddress((void**)&h,    g_h);
    cudaGetSymbolAddress((void**)&Bk,   g_Bk);
    cudaGetSymbolAddress((void**)&zqhi, g_zqhi);
    cudaGetSymbolAddress((void**)&zqlo, g_zqlo);
    cudaGetSymbolAddress((void**)&h2hi, g_h2hi);
    cudaGetSymbolAddress((void**)&h2lo, g_h2lo);
    cudaGetSymbolAddress((void**)&w3hi, g_w3hi);
    cudaGetSymbolAddress((void**)&w3lo, g_w3lo);
    cudaGetSymbolAddress((void**)&w4hi, g_w4hi);
    cudaGetSymbolAddress((void**)&w4lo, g_w4lo);
    cudaGetSymbolAddress((void**)&ehi,  g_ehi);
    cudaGetSymbolAddress((void**)&elo,  g_elo);

    static int attr_set = 0;
    if (!attr_set) {
        cudaFuncSetAttribute(gemm_wmma<0>,
            cudaFuncAttributeMaxDynamicSharedMemorySize, SM_TOTAL);
        cudaFuncSetAttribute(gemm_wmma<1>,
            cudaFuncAttributeMaxDynamicSharedMemorySize, SM_TOTAL);
        attr_set = 1;
    }

    // prep (input-only dependent)
    bk_kernel<<<(KCODES * 32 + 255) / 256, 256>>>(emb, Bk);
    splitf<<<(KCODES * DDIM) / 1024, 256>>>(emb, ehi, elo);
    splitf<<<((size_t)HID * HID) / 1024, 256>>>(W3, w3hi, w3lo);
    splitf<<<((size_t)HID * IN_DIM) / 1024, 256>>>(W4, w4hi, w4lo);

    // encoder (bit-frozen)
    sgemm<true ><<<dim3(HID / 128, B_ / 128), 256>>>(x, W1, b1, h, B_, HID, IN_DIM);
    sgemm<false><<<dim3(HID / 128, B_ / 128), 256>>>(h, W2, b2, z, B_, HID, HID);
    vq_kernel<<<(B_ * LLAT) / 32, 256>>>(z, emb, Bk, ehi, elo, zq, zqhi, zqlo, idxf);

    // decoder (wmma bf16x3, cp.async double-buffered, 2 CTAs/SM)
    gemm_wmma<1><<<dim3(HID / 128, B_ / 128), 256, SM_TOTAL>>>(
        zqhi, zqlo, w3hi, w3lo, b3, nullptr, h2hi, h2lo, HID, HID);
    gemm_wmma<0><<<dim3(IN_DIM / 128, B_ / 128), 256, SM_TOTAL>>>(
        h2hi, h2lo, w4hi, w4lo, b4, x_recon, nullptr, nullptr, IN_DIM, HID);
}